// round 10
// baseline (speedup 1.0000x reference)
#include <cuda_runtime.h>
#include <math.h>

#define NN 100000
#define EE 3200000
#define IN_F 256
#define ATT_D 128
#define SLOPE 0.2f

// ---------------- device scratch (no runtime allocation allowed) ----------
__device__ float g_wsrc[IN_F];
__device__ float g_wdst[IN_F];
__device__ float g_ssrc[NN];
__device__ float g_sdst[NN];
__device__ float g_denom[NN];
__device__ float g_rden[NN + 4];
__device__ int   g_is64;            // 1 if edge buffer is int64, 0 if int32

// ---------------- fused pre: zero denom | wvec | dtype sniff ----------------
__global__ void k_pre(const float* __restrict__ W, const float* __restrict__ a,
                      const long long* __restrict__ edge, int n, int B0) {
    int b = blockIdx.x;
    if (b < B0) {
        int i = b * blockDim.x + threadIdx.x;
        if (i < n) g_denom[i] = 0.0f;
    } else if (b == B0) {
        __shared__ float sa[2 * ATT_D];
        int t = threadIdx.x;            // 256 threads
        sa[t] = a[t];
        __syncthreads();
        const float* row = W + (size_t)t * ATT_D;
        float ws = 0.f, wd = 0.f;
#pragma unroll 8
        for (int j = 0; j < ATT_D; ++j) {
            float w = row[j];
            ws += w * sa[j];
            wd += w * sa[ATT_D + j];
        }
        g_wsrc[t] = ws;
        g_wdst[t] = wd;
    } else {
        // dtype sniff: int32 data read as int64 exits [0,n) with prob ~1
        if (threadIdx.x == 0) {
            int is64 = 1;
            for (int i = 0; i < 256; ++i) {
                long long v = edge[i];
                if (v < 0 || v >= (long long)n) { is64 = 0; break; }
            }
            g_is64 = is64;
        }
    }
}

// ---------------- node scores: 2 rows per warp (4 LDG.128 in flight) --------
__global__ void k_node_scores(const float* __restrict__ x, int n) {
    int gw   = (blockIdx.x * blockDim.x + threadIdx.x) >> 5;
    int lane = threadIdx.x & 31;
    int r0 = gw * 2, r1 = r0 + 1;
    if (r0 >= n) return;
    bool has1 = (r1 < n);
    const float4* x0 = reinterpret_cast<const float4*>(x + (size_t)r0 * IN_F);
    const float4* x1 = reinterpret_cast<const float4*>(x + (size_t)(has1 ? r1 : r0) * IN_F);
    const float4* ws = reinterpret_cast<const float4*>(g_wsrc);
    const float4* wd = reinterpret_cast<const float4*>(g_wdst);
    float a00 = 0.f, a01 = 0.f, a10 = 0.f, a11 = 0.f;
#pragma unroll
    for (int k = 0; k < IN_F / 4 / 32; ++k) {   // 2 iters
        float4 v0 = x0[lane + 32 * k];
        float4 v1 = x1[lane + 32 * k];
        float4 sv = __ldg(&ws[lane + 32 * k]);
        float4 dv = __ldg(&wd[lane + 32 * k]);
        a00 += v0.x * sv.x + v0.y * sv.y + v0.z * sv.z + v0.w * sv.w;
        a01 += v0.x * dv.x + v0.y * dv.y + v0.z * dv.z + v0.w * dv.w;
        a10 += v1.x * sv.x + v1.y * sv.y + v1.z * sv.z + v1.w * sv.w;
        a11 += v1.x * dv.x + v1.y * dv.y + v1.z * dv.z + v1.w * dv.w;
    }
#pragma unroll
    for (int off = 16; off; off >>= 1) {
        a00 += __shfl_xor_sync(0xffffffffu, a00, off);
        a01 += __shfl_xor_sync(0xffffffffu, a01, off);
        a10 += __shfl_xor_sync(0xffffffffu, a10, off);
        a11 += __shfl_xor_sync(0xffffffffu, a11, off);
    }
    if (lane == 0) {
        g_ssrc[r0] = a00;
        g_sdst[r0] = a01;
        if (has1) { g_ssrc[r1] = a10; g_sdst[r1] = a11; }
    }
}

// ---------------- edge pass 1: ex = exp(leaky(score)); segment-sum ----------
// Hot path: int32 edges, 8 edges/thread, register-lean. int64 / tail fall
// back to a scalar loop (the real data is int32; sniff proved it in R5-R9).
// No max subtraction: scores analytically bounded (|s| < ~30 << 88).
__global__ void __launch_bounds__(256) k_edgeB(const void* __restrict__ edge_raw,
                                               float* __restrict__ out,
                                               int e_cnt, int n) {
    int i = (blockIdx.x * blockDim.x + threadIdx.x) << 3;
    if (i >= e_cnt) return;
    const unsigned nm1 = (unsigned)(n - 1);
    if (!g_is64 && i + 7 < e_cnt) {
        const int* ep = (const int*)edge_raw;
        int4 s0 = *(const int4*)(ep + i);
        int4 s1 = *(const int4*)(ep + i + 4);
        int4 d0 = *(const int4*)(ep + (size_t)e_cnt + i);
        int4 d1 = *(const int4*)(ep + (size_t)e_cnt + i + 4);
        unsigned sa0 = min((unsigned)s0.x, nm1), sa1 = min((unsigned)s0.y, nm1);
        unsigned sa2 = min((unsigned)s0.z, nm1), sa3 = min((unsigned)s0.w, nm1);
        unsigned sa4 = min((unsigned)s1.x, nm1), sa5 = min((unsigned)s1.y, nm1);
        unsigned sa6 = min((unsigned)s1.z, nm1), sa7 = min((unsigned)s1.w, nm1);
        // issue all 16 gathers before any exp
        float v0 = g_ssrc[sa0] + g_sdst[min((unsigned)d0.x, nm1)];
        float v1 = g_ssrc[sa1] + g_sdst[min((unsigned)d0.y, nm1)];
        float v2 = g_ssrc[sa2] + g_sdst[min((unsigned)d0.z, nm1)];
        float v3 = g_ssrc[sa3] + g_sdst[min((unsigned)d0.w, nm1)];
        float v4 = g_ssrc[sa4] + g_sdst[min((unsigned)d1.x, nm1)];
        float v5 = g_ssrc[sa5] + g_sdst[min((unsigned)d1.y, nm1)];
        float v6 = g_ssrc[sa6] + g_sdst[min((unsigned)d1.z, nm1)];
        float v7 = g_ssrc[sa7] + g_sdst[min((unsigned)d1.w, nm1)];
        v0 = (v0 >= 0.f) ? v0 : SLOPE * v0;  v0 = __expf(v0);
        v1 = (v1 >= 0.f) ? v1 : SLOPE * v1;  v1 = __expf(v1);
        v2 = (v2 >= 0.f) ? v2 : SLOPE * v2;  v2 = __expf(v2);
        v3 = (v3 >= 0.f) ? v3 : SLOPE * v3;  v3 = __expf(v3);
        v4 = (v4 >= 0.f) ? v4 : SLOPE * v4;  v4 = __expf(v4);
        v5 = (v5 >= 0.f) ? v5 : SLOPE * v5;  v5 = __expf(v5);
        v6 = (v6 >= 0.f) ? v6 : SLOPE * v6;  v6 = __expf(v6);
        v7 = (v7 >= 0.f) ? v7 : SLOPE * v7;  v7 = __expf(v7);
        *reinterpret_cast<float4*>(out + i)     = make_float4(v0, v1, v2, v3);
        *reinterpret_cast<float4*>(out + i + 4) = make_float4(v4, v5, v6, v7);
        atomicAdd(&g_denom[sa0], v0);
        atomicAdd(&g_denom[sa1], v1);
        atomicAdd(&g_denom[sa2], v2);
        atomicAdd(&g_denom[sa3], v3);
        atomicAdd(&g_denom[sa4], v4);
        atomicAdd(&g_denom[sa5], v5);
        atomicAdd(&g_denom[sa6], v6);
        atomicAdd(&g_denom[sa7], v7);
    } else {
        // generic fallback: int64 whole-buffer case, or int32 tail
        const int is64 = g_is64;
        for (int k = 0; k < 8; ++k) {
            int e = i + k;
            if (e >= e_cnt) break;
            int src, dst;
            if (is64) {
                const long long* ep = (const long long*)edge_raw;
                src = (int)ep[e];
                dst = (int)ep[(size_t)e_cnt + e];
            } else {
                const int* ep = (const int*)edge_raw;
                src = ep[e];
                dst = ep[(size_t)e_cnt + e];
            }
            unsigned ss = min((unsigned)src, nm1);
            unsigned dd = min((unsigned)dst, nm1);
            float s = g_ssrc[ss] + g_sdst[dd];
            s = (s >= 0.f) ? s : SLOPE * s;
            float ex = __expf(s);
            out[e] = ex;
            atomicAdd(&g_denom[ss], ex);
        }
    }
}

// ---------------- reciprocal: 100k RCPs instead of 3.2M divides --------------
__global__ void k_recip(int n) {
    int i = blockIdx.x * blockDim.x + threadIdx.x;
    if (i < n) g_rden[i] = 1.0f / (g_denom[i] + 1e-16f);
}

// ---------------- edge pass 2: out *= rden[src] ------------------------------
__global__ void __launch_bounds__(256) k_edgeC(const void* __restrict__ edge_raw,
                                               float* __restrict__ out,
                                               int e_cnt, int n) {
    int i = (blockIdx.x * blockDim.x + threadIdx.x) << 3;
    if (i >= e_cnt) return;
    const unsigned nm1 = (unsigned)(n - 1);
    if (!g_is64 && i + 7 < e_cnt) {
        const int* ep = (const int*)edge_raw;
        int4 s0 = *(const int4*)(ep + i);
        int4 s1 = *(const int4*)(ep + i + 4);
        float4 v0 = *reinterpret_cast<const float4*>(out + i);
        float4 v1 = *reinterpret_cast<const float4*>(out + i + 4);
        v0.x *= g_rden[min((unsigned)s0.x, nm1)];
        v0.y *= g_rden[min((unsigned)s0.y, nm1)];
        v0.z *= g_rden[min((unsigned)s0.z, nm1)];
        v0.w *= g_rden[min((unsigned)s0.w, nm1)];
        v1.x *= g_rden[min((unsigned)s1.x, nm1)];
        v1.y *= g_rden[min((unsigned)s1.y, nm1)];
        v1.z *= g_rden[min((unsigned)s1.z, nm1)];
        v1.w *= g_rden[min((unsigned)s1.w, nm1)];
        *reinterpret_cast<float4*>(out + i)     = v0;
        *reinterpret_cast<float4*>(out + i + 4) = v1;
    } else {
        const int is64 = g_is64;
        for (int k = 0; k < 8; ++k) {
            int e = i + k;
            if (e >= e_cnt) break;
            int src;
            if (is64) src = (int)((const long long*)edge_raw)[e];
            else      src = ((const int*)edge_raw)[e];
            out[e] *= g_rden[min((unsigned)src, nm1)];
        }
    }
}

// ---------------- launch ------------------------------------------------------
extern "C" void kernel_launch(void* const* d_in, const int* in_sizes, int n_in,
                              void* d_out, int out_size) {
    const float* x    = (const float*)d_in[0];   // [N, 256] f32
    const void*  edge = d_in[1];                  // [2, E] int32 or int64
    const float* W    = (const float*)d_in[2];   // [256, 128] f32
    const float* a    = (const float*)d_in[3];   // [256] f32
    float* out = (float*)d_out;                   // [E, 1] f32

    const int n = in_sizes[0] / IN_F;   // 100000
    const int e = out_size;             // 3200000

    const int B0 = (n + 255) / 256;
    k_pre<<<B0 + 2, 256>>>(W, a, (const long long*)edge, n, B0);
    k_node_scores<<<(n + 15) / 16, 256>>>(x, n);          // 2 rows per warp
    const int eb = (e / 8 + 255) / 256;
    k_edgeB<<<eb, 256>>>(edge, out, e, n);
    k_recip<<<(n + 255) / 256, 256>>>(n);
    k_edgeC<<<eb, 256>>>(edge, out, e, n);
}

// round 11
// speedup vs baseline: 1.0925x; 1.0925x over previous
#include <cuda_runtime.h>
#include <math.h>

#define NN 100000
#define EE 3200000
#define IN_F 256
#define ATT_D 128
#define SLOPE 0.2f

// ---------------- device scratch (no runtime allocation allowed) ----------
__device__ float g_wsrc[IN_F];
__device__ float g_wdst[IN_F];
__device__ float g_ssrc[NN];
__device__ float g_sdst[NN];
__device__ float g_denom[NN];
__device__ int   g_is64;     // 1 if edge buffer is int64, 0 if int32

// ---------------- fused pre-pass -------------------------------------------
// blocks [0, B0): zero denom
// block  B0     : w_src = W @ a[:128], w_dst = W @ a[128:]
// block  B0+1   : edge dtype sniff
__global__ void k_pre(const float* __restrict__ W, const float* __restrict__ a,
                      const long long* __restrict__ edge, int n, int B0) {
    int b = blockIdx.x;
    if (b < B0) {
        int i = b * blockDim.x + threadIdx.x;
        if (i < n) g_denom[i] = 0.0f;
    } else if (b == B0) {
        __shared__ float sa[2 * ATT_D];
        int t = threadIdx.x;            // 256 threads
        sa[t] = a[t];
        __syncthreads();
        const float* row = W + (size_t)t * ATT_D;
        float ws = 0.f, wd = 0.f;
#pragma unroll 8
        for (int j = 0; j < ATT_D; ++j) {
            float w = row[j];
            ws += w * sa[j];
            wd += w * sa[ATT_D + j];
        }
        g_wsrc[t] = ws;
        g_wdst[t] = wd;
    } else {
        // dtype sniff: if the buffer is really int32, reading pairs as int64
        // yields out-of-range values with probability ~1 per probe.
        if (threadIdx.x == 0) {
            int is64 = 1;
            for (int i = 0; i < 256; ++i) {
                long long v = edge[i];
                if (v < 0 || v >= (long long)n) { is64 = 0; break; }
            }
            g_is64 = is64;
        }
    }
}

// ---------------- node scores (near roofline already) -----------------------
__global__ void k_node_scores(const float* __restrict__ x, int n) {
    int gw   = (blockIdx.x * blockDim.x + threadIdx.x) >> 5;
    int lane = threadIdx.x & 31;
    if (gw >= n) return;
    const float4* xr = reinterpret_cast<const float4*>(x + (size_t)gw * IN_F);
    const float4* ws = reinterpret_cast<const float4*>(g_wsrc);
    const float4* wd = reinterpret_cast<const float4*>(g_wdst);
    float a0 = 0.f, a1 = 0.f;
#pragma unroll
    for (int k = 0; k < IN_F / 4 / 32; ++k) {   // 2 iters
        float4 xv = xr[lane + 32 * k];
        float4 sv = __ldg(&ws[lane + 32 * k]);
        float4 dv = __ldg(&wd[lane + 32 * k]);
        a0 += xv.x * sv.x + xv.y * sv.y + xv.z * sv.z + xv.w * sv.w;
        a1 += xv.x * dv.x + xv.y * dv.y + xv.z * dv.z + xv.w * dv.w;
    }
#pragma unroll
    for (int off = 16; off; off >>= 1) {
        a0 += __shfl_xor_sync(0xffffffffu, a0, off);
        a1 += __shfl_xor_sync(0xffffffffu, a1, off);
    }
    if (lane == 0) {
        g_ssrc[gw] = a0;
        g_sdst[gw] = a1;
    }
}

// ---------------- edge pass 1: ex = exp(leaky(score)); segment-sum by src ---
// 4 edges per thread, 128-bit loads/stores. No max subtraction: scores are
// analytically bounded (|score| < ~30 << 88), so exp() cannot overflow and
// the normalized ratio is identical to the max-subtracted form.
__global__ void k_edgeB(const void* __restrict__ edge_raw,
                        float* __restrict__ out, int e_cnt, int n) {
    int i = (blockIdx.x * blockDim.x + threadIdx.x) << 2;
    if (i >= e_cnt) return;
    const unsigned nm1 = (unsigned)(n - 1);
    int src[4], dst[4];
    bool full = (i + 3 < e_cnt);
    if (g_is64) {
        const long long* ep = (const long long*)edge_raw;
        if (full) {
            longlong2 s0 = *(const longlong2*)(ep + i);
            longlong2 s1 = *(const longlong2*)(ep + i + 2);
            longlong2 d0 = *(const longlong2*)(ep + (size_t)e_cnt + i);
            longlong2 d1 = *(const longlong2*)(ep + (size_t)e_cnt + i + 2);
            src[0] = (int)s0.x; src[1] = (int)s0.y; src[2] = (int)s1.x; src[3] = (int)s1.y;
            dst[0] = (int)d0.x; dst[1] = (int)d0.y; dst[2] = (int)d1.x; dst[3] = (int)d1.y;
        } else {
            for (int k = 0; k < 4; ++k) {
                int e = min(i + k, e_cnt - 1);
                src[k] = (int)ep[e];
                dst[k] = (int)ep[(size_t)e_cnt + e];
            }
        }
    } else {
        const int* ep = (const int*)edge_raw;
        if (full) {
            int4 s = *(const int4*)(ep + i);
            int4 d = *(const int4*)(ep + (size_t)e_cnt + i);
            src[0] = s.x; src[1] = s.y; src[2] = s.z; src[3] = s.w;
            dst[0] = d.x; dst[1] = d.y; dst[2] = d.z; dst[3] = d.w;
        } else {
            for (int k = 0; k < 4; ++k) {
                int e = min(i + k, e_cnt - 1);
                src[k] = ep[e];
                dst[k] = ep[(size_t)e_cnt + e];
            }
        }
    }
    float ex[4];
#pragma unroll
    for (int k = 0; k < 4; ++k) {
        unsigned ss = min((unsigned)src[k], nm1);   // clamp: safety, no-op normally
        unsigned dd = min((unsigned)dst[k], nm1);
        src[k] = (int)ss;
        float s = g_ssrc[ss] + g_sdst[dd];
        s = (s >= 0.f) ? s : SLOPE * s;
        ex[k] = __expf(s);
    }
    if (full) {
        *reinterpret_cast<float4*>(out + i) = make_float4(ex[0], ex[1], ex[2], ex[3]);
#pragma unroll
        for (int k = 0; k < 4; ++k) atomicAdd(&g_denom[src[k]], ex[k]);
    } else {
        for (int k = 0; k < 4 && i + k < e_cnt; ++k) {
            out[i + k] = ex[k];
            atomicAdd(&g_denom[src[k]], ex[k]);
        }
    }
}

// ---------------- edge pass 2: normalize (fast division) --------------------
__global__ void k_edgeC(const void* __restrict__ edge_raw,
                        float* __restrict__ out, int e_cnt, int n) {
    int i = (blockIdx.x * blockDim.x + threadIdx.x) << 2;
    if (i >= e_cnt) return;
    const unsigned nm1 = (unsigned)(n - 1);
    int src[4];
    bool full = (i + 3 < e_cnt);
    if (g_is64) {
        const long long* ep = (const long long*)edge_raw;
        if (full) {
            longlong2 s0 = *(const longlong2*)(ep + i);
            longlong2 s1 = *(const longlong2*)(ep + i + 2);
            src[0] = (int)s0.x; src[1] = (int)s0.y; src[2] = (int)s1.x; src[3] = (int)s1.y;
        } else {
            for (int k = 0; k < 4; ++k) src[k] = (int)ep[min(i + k, e_cnt - 1)];
        }
    } else {
        const int* ep = (const int*)edge_raw;
        if (full) {
            int4 s = *(const int4*)(ep + i);
            src[0] = s.x; src[1] = s.y; src[2] = s.z; src[3] = s.w;
        } else {
            for (int k = 0; k < 4; ++k) src[k] = ep[min(i + k, e_cnt - 1)];
        }
    }
    if (full) {
        float4 v = *reinterpret_cast<const float4*>(out + i);
        v.x = __fdividef(v.x, g_denom[min((unsigned)src[0], nm1)] + 1e-16f);
        v.y = __fdividef(v.y, g_denom[min((unsigned)src[1], nm1)] + 1e-16f);
        v.z = __fdividef(v.z, g_denom[min((unsigned)src[2], nm1)] + 1e-16f);
        v.w = __fdividef(v.w, g_denom[min((unsigned)src[3], nm1)] + 1e-16f);
        *reinterpret_cast<float4*>(out + i) = v;
    } else {
        for (int k = 0; k < 4 && i + k < e_cnt; ++k)
            out[i + k] = __fdividef(out[i + k],
                                    g_denom[min((unsigned)src[k], nm1)] + 1e-16f);
    }
}

// ---------------- launch ------------------------------------------------------
extern "C" void kernel_launch(void* const* d_in, const int* in_sizes, int n_in,
                              void* d_out, int out_size) {
    const float* x    = (const float*)d_in[0];   // [N, 256] f32
    const void*  edge = d_in[1];                  // [2, E] int32 or int64
    const float* W    = (const float*)d_in[2];   // [256, 128] f32
    const float* a    = (const float*)d_in[3];   // [256] f32
    float* out = (float*)d_out;                   // [E, 1] f32

    const int n = in_sizes[0] / IN_F;   // 100000
    const int e = out_size;             // 3200000

    const int B0 = (n + 255) / 256;
    k_pre<<<B0 + 2, 256>>>(W, a, (const long long*)edge, n, B0);
    k_node_scores<<<(n + 7) / 8, 256>>>(x, n);          // one warp per row
    const int eb = (e / 4 + 255) / 256;
    k_edgeB<<<eb, 256>>>(edge, out, e, n);
    k_edgeC<<<eb, 256>>>(edge, out, e, n);
}